// round 1
// baseline (speedup 1.0000x reference)
#include <cuda_runtime.h>

// ---------------------------------------------------------------------------
// LIF SNN: 16 timesteps of conv0(2->32) -> LIF -> conv1(32->64) -> LIF ->
// maxpool2 -> dense0(65536->512) -> LIF -> dense1(512->11) -> LIF -> acc.
// B=16, H=W=64. All fp32; spikes stored as bytes; f32x2 packed FMA for the
// two compute hot spots (conv1: pack 2 out-channels, dense0: pack 2 batches).
// ---------------------------------------------------------------------------

#define DECAYF 0.951229424500714f   // exp(-1/20), rounded to f32 by compiler

// Persistent state (zero-alloc scratch: __device__ globals)
__device__ float         g_vm0[2097152];      // [16][32][64][64]
__device__ unsigned char g_s0 [2097152];
__device__ float         g_vm1[4194304];      // [16][64][64][64]
__device__ unsigned char g_s1 [4194304];
__device__ float         g_flatT[1048576];    // pooled spikes, layout [i=65536][b=16]
__device__ float         g_part[131072];      // dense0 partials [is=16][j=512][b=16]
__device__ float         g_vm2[8192], g_s2[8192];   // [b=16][j=512]
__device__ float         g_vm3[176],  g_s3[176], g_acc[176];

// ---- packed f32x2 helpers ----
__device__ __forceinline__ unsigned long long pack2(float a, float b) {
    unsigned long long r;
    asm("mov.b64 %0, {%1, %2};" : "=l"(r)
        : "r"(__float_as_uint(a)), "r"(__float_as_uint(b)));
    return r;
}
__device__ __forceinline__ void unpack2(unsigned long long v, float& a, float& b) {
    unsigned lo, hi;
    asm("mov.b64 {%0, %1}, %2;" : "=r"(lo), "=r"(hi) : "l"(v));
    a = __uint_as_float(lo); b = __uint_as_float(hi);
}
#define FMA2(acc, w, s) asm("fma.rn.f32x2 %0, %1, %2, %0;" : "+l"(acc) : "l"(w), "l"(s))
#define ADD2(acc, v)    asm("add.rn.f32x2 %0, %0, %1;"      : "+l"(acc) : "l"(v))

// ---------------------------------------------------------------------------
// Kernel 1: conv0 (3x3, pad 1) + LIF0.  grid = 16 b * 32 och = 512 blocks.
// ---------------------------------------------------------------------------
__global__ void __launch_bounds__(256) k_conv0(const float* __restrict__ in,
                                               const float* __restrict__ W0, int t)
{
    int bid = blockIdx.x;
    int o = bid & 31, b = bid >> 5;
    float w[18];
#pragma unroll
    for (int i = 0; i < 18; i++) w[i] = W0[o * 18 + i];
    const float* x0 = in + (((long)(b * 16 + t)) << 13);   // [b][t][c=2][64][64]

    for (int p = threadIdx.x; p < 4096; p += 256) {
        int y = p >> 6, x = p & 63;
        float acc = 0.f;
#pragma unroll
        for (int c = 0; c < 2; c++) {
#pragma unroll
            for (int ky = 0; ky < 3; ky++) {
                int yy = y + ky - 1;
                if ((unsigned)yy < 64u) {
#pragma unroll
                    for (int kx = 0; kx < 3; kx++) {
                        int xx = x + kx - 1;
                        if ((unsigned)xx < 64u) {
                            float v = x0[(c << 12) + (yy << 6) + xx];
                            v = fminf(fmaxf(v, 0.f), 1.f);   // clip(x,0,1)
                            acc = fmaf(w[c * 9 + ky * 3 + kx], v, acc);
                        }
                    }
                }
            }
        }
        long idx = (((long)bid) << 12) + p;
        float vm = t ? g_vm0[idx] * DECAYF * (1.f - (float)g_s0[idx]) + acc : acc;
        g_vm0[idx] = vm;
        g_s0[idx]  = vm > 0.5f ? (unsigned char)1 : (unsigned char)0;
    }
}

// ---------------------------------------------------------------------------
// Kernel 2: conv1 (32->64, 3x3) + LIF1 + fused maxpool2 -> g_flatT.
// grid = 16 b * 16 tiles(16x16 px) * 2 och-groups(32) = 512 blocks, 256 thr.
// Each thread: 1 pixel, 32 out-channels as 16 packed f32x2 accumulators.
// smem: paired weights (36864 B) + spike halo tile 32x18x18 bytes (10368 B).
// ---------------------------------------------------------------------------
__global__ void __launch_bounds__(256) k_conv1(const float* __restrict__ W1, int t)
{
    extern __shared__ unsigned char sh1[];
    unsigned long long* wsm = (unsigned long long*)sh1;      // [c*9+k][16] pairs
    unsigned char*      ssm = sh1 + 36864;                   // [c][18][18]

    int bid  = blockIdx.x;
    int og   = bid & 1;
    int tile = (bid >> 1) & 15;
    int b    = bid >> 5;
    int ty0  = (tile >> 2) << 4, tx0 = (tile & 3) << 4;
    int tid  = threadIdx.x;

    // weights: W1[o][c][3][3] = W1[o*288 + ck] ; pair (o, o+1)
    for (int idx = tid; idx < 4608; idx += 256) {
        int ck = idx >> 4, g = idx & 15;
        int o  = (og << 5) + (g << 1);
        wsm[idx] = pack2(W1[o * 288 + ck], W1[(o + 1) * 288 + ck]);
    }
    // spike halo tile (zero padded)
    int ybase = ty0 - 1, xbase = tx0 - 1;
    for (int idx = tid; idx < 10368; idx += 256) {
        int c = idx / 324, r = idx - c * 324;
        int yy = r / 18, xx = r - yy * 18;
        int y = ybase + yy, x = xbase + xx;
        unsigned char v = 0;
        if ((unsigned)y < 64u && (unsigned)x < 64u)
            v = g_s0[(((b << 5) + c) << 12) + (y << 6) + x];
        ssm[idx] = v;
    }
    __syncthreads();

    int tx = tid & 15, ty = tid >> 4;
    unsigned long long acc[16];
#pragma unroll
    for (int g = 0; g < 16; g++) acc[g] = 0ull;

    const unsigned char* sp = ssm + ty * 18 + tx;
    for (int c = 0; c < 32; c++) {
#pragma unroll
        for (int k = 0; k < 9; k++) {
            float s = (float)sp[c * 324 + (k / 3) * 18 + (k % 3)];
            unsigned long long s2 = pack2(s, s);
            const unsigned long long* wc = wsm + c * 144 + k * 16;
#pragma unroll
            for (int g = 0; g < 16; g++) FMA2(acc[g], wc[g], s2);
        }
    }

    int y = ty0 + ty, x = tx0 + tx;
    unsigned m = 0;
#pragma unroll
    for (int g = 0; g < 16; g++) {
        float I0, I1; unpack2(acc[g], I0, I1);
        int o0 = (og << 5) + (g << 1);
        long i0 = (((long)((b << 6) + o0)) << 12) + (y << 6) + x;
        float va = t ? g_vm1[i0]        * DECAYF * (1.f - (float)g_s1[i0])        + I0 : I0;
        float vb = t ? g_vm1[i0 + 4096] * DECAYF * (1.f - (float)g_s1[i0 + 4096]) + I1 : I1;
        g_vm1[i0] = va; g_vm1[i0 + 4096] = vb;
        unsigned sa = va > 0.5f ? 1u : 0u;
        unsigned sb = vb > 0.5f ? 1u : 0u;
        g_s1[i0]        = (unsigned char)sa;
        g_s1[i0 + 4096] = (unsigned char)sb;
        m |= (sa << (g * 2)) | (sb << (g * 2 + 1));
    }
    // maxpool2 over binary spikes = OR across the 2x2 neighborhood
    m |= __shfl_xor_sync(0xffffffffu, m, 1);    // tx pair
    m |= __shfl_xor_sync(0xffffffffu, m, 16);   // ty pair
    if (((tx | ty) & 1) == 0) {
        int py = y >> 1, px = x >> 1;
        int ibase = ((og << 5) << 10) + (py << 5) + px;   // i = o*1024 + py*32 + px
#pragma unroll
        for (int l = 0; l < 32; l++)
            g_flatT[((ibase + (l << 10)) << 4) + b] = (float)((m >> l) & 1u);
    }
}

// ---------------------------------------------------------------------------
// Kernel 3: dense0 partials. out[b][j] = sum_i flat[b][i] * D0[j][i].
// grid = 32 j-tiles(16) x 16 i-splits(4096) = 512 blocks, 256 thr.
// smem: 1024-i chunk of flat for all 16 batches as 8 f32x2 pair rows (64 KB).
// thread (jl,ig) accumulates 16 batches (8 packed) over i = ig mod 16.
// Deterministic: butterfly-shuffle reduce + fixed-order partial sum in tail.
// ---------------------------------------------------------------------------
__global__ void __launch_bounds__(256) k_dense0(const float* __restrict__ D0)
{
    extern __shared__ float sh[];                         // 16384 floats
    unsigned long long* sb2 = (unsigned long long*)sh;    // [p=8][1024]
    int jt = blockIdx.x & 31;
    int is = blockIdx.x >> 5;
    int tid = threadIdx.x;
    int jl = tid >> 4, ig = tid & 15;
    int j  = (jt << 4) + jl;
    const float* drow = D0 + ((long)j << 16) + ((long)is << 12);

    unsigned long long acc[8];
#pragma unroll
    for (int p = 0; p < 8; p++) acc[p] = 0ull;

    for (int ch = 0; ch < 4; ch++) {
        const float4* src = (const float4*)(g_flatT + ((((is << 2) + ch) << 10) << 4));
        for (int n = tid; n < 4096; n += 256) {           // 16384 floats / 4
            float4 v = src[n];
            int e = n << 2;
            int i = e >> 4, b0 = e & 15;                  // b0 in {0,4,8,12}
            int base = ((b0 >> 1) << 11) + (i << 1);
            sh[base]        = v.x;  sh[base + 1]    = v.y;
            sh[base + 2048] = v.z;  sh[base + 2049] = v.w;
        }
        __syncthreads();
        const float* dch = drow + (ch << 10);
#pragma unroll 8
        for (int n = 0; n < 64; n++) {
            int i = ig + (n << 4);
            float d = dch[i];
            unsigned long long d2 = pack2(d, d);
#pragma unroll
            for (int p = 0; p < 8; p++) FMA2(acc[p], sb2[(p << 10) + i], d2);
        }
        __syncthreads();
    }
    // reduce over the 16 ig lanes (within half-warp groups) — deterministic
#pragma unroll
    for (int off = 8; off; off >>= 1) {
#pragma unroll
        for (int p = 0; p < 8; p++) {
            unsigned long long v = __shfl_xor_sync(0xffffffffu, acc[p], off);
            ADD2(acc[p], v);
        }
    }
    if (ig == 0) {
        float* dst = g_part + ((((long)is << 9) + j) << 4);
#pragma unroll
        for (int p = 0; p < 8; p++) {
            float a0, a1; unpack2(acc[p], a0, a1);
            dst[2 * p] = a0; dst[2 * p + 1] = a1;
        }
    }
}

// ---------------------------------------------------------------------------
// Kernel 4: tail — reduce dense0 partials, LIF2, dense1, LIF3, accumulate,
// and write output at t==15.  Single block of 512 threads.
// ---------------------------------------------------------------------------
__global__ void __launch_bounds__(512) k_tail(const float* __restrict__ D1,
                                              float* __restrict__ out, int t)
{
    __shared__ float s2f[8192];
    int tid = threadIdx.x;
    for (int e = tid; e < 8192; e += 512) {
        int j = e >> 4, b = e & 15;
        float I = 0.f;
#pragma unroll
        for (int is = 0; is < 16; is++) I += g_part[(is << 13) + (j << 4) + b];
        int idx = (b << 9) + j;
        float vm = t ? g_vm2[idx] * DECAYF * (1.f - g_s2[idx]) + I : I;
        float s  = vm > 0.5f ? 1.f : 0.f;
        g_vm2[idx] = vm; g_s2[idx] = s; s2f[idx] = s;
    }
    __syncthreads();
    if (tid < 176) {
        int b = tid / 11, k = tid - b * 11;
        const float* sv = s2f + (b << 9);
        const float* dk = D1 + (k << 9);
        float acc = 0.f;
#pragma unroll 8
        for (int jj = 0; jj < 512; jj++) acc = fmaf(sv[jj], dk[jj], acc);
        float vm = t ? g_vm3[tid] * DECAYF * (1.f - g_s3[tid]) + acc : acc;
        float s  = vm > 0.5f ? 1.f : 0.f;
        g_vm3[tid] = vm; g_s3[tid] = s;
        float a = (t ? g_acc[tid] : 0.f) + s;
        g_acc[tid] = a;
        if (t == 15) out[tid] = a * 0.0625f;   // acc / num_steps
    }
}

// ---------------------------------------------------------------------------
extern "C" void kernel_launch(void* const* d_in, const int* in_sizes, int n_in,
                              void* d_out, int out_size)
{
    (void)in_sizes; (void)n_in; (void)out_size;
    const float* input = (const float*)d_in[0];
    const float* W0    = (const float*)d_in[1];
    const float* W1    = (const float*)d_in[2];
    const float* D0    = (const float*)d_in[3];
    const float* D1    = (const float*)d_in[4];
    float* out = (float*)d_out;

    cudaFuncSetAttribute(k_dense0, cudaFuncAttributeMaxDynamicSharedMemorySize, 65536);

    for (int t = 0; t < 16; t++) {
        k_conv0 <<<512, 256>>>(input, W0, t);
        k_conv1 <<<512, 256, 47232>>>(W1, t);
        k_dense0<<<512, 256, 65536>>>(D0);
        k_tail  <<<1, 512>>>(D1, out, t);
    }
}

// round 2
// speedup vs baseline: 1.3005x; 1.3005x over previous
#include <cuda_runtime.h>

#define DECAYF 0.951229424500714f   // exp(-1/20)

// Persistent state (no allocs allowed)
__device__ float         g_vm0[2097152];      // [16 b][32 o][64][64]
__device__ unsigned char g_s0 [2097152];
__device__ float         g_vm1[4194304];      // [16 b][64 o][64][64]
__device__ unsigned char g_s1 [4194304];
__device__ float         g_flatT[1048576];    // pooled spikes [i=65536][b=16]
__device__ float         g_part[524288];      // dense0 partials [is=64][j=512][b=16]
__device__ float         g_vm2[8192], g_s2f[8192];   // [b][j]
__device__ float         g_vm3[176],  g_s3[176], g_acc[176];

// ---- packed f32x2 helpers ----
__device__ __forceinline__ unsigned long long pack2(float a, float b) {
    unsigned long long r;
    asm("mov.b64 %0, {%1, %2};" : "=l"(r)
        : "r"(__float_as_uint(a)), "r"(__float_as_uint(b)));
    return r;
}
__device__ __forceinline__ void unpack2(unsigned long long v, float& a, float& b) {
    unsigned lo, hi;
    asm("mov.b64 {%0, %1}, %2;" : "=r"(lo), "=r"(hi) : "l"(v));
    a = __uint_as_float(lo); b = __uint_as_float(hi);
}
#define FMA2(acc, w, s) asm("fma.rn.f32x2 %0, %1, %2, %0;" : "+l"(acc) : "l"(w), "l"(s))
#define ADD2(acc, v)    asm("add.rn.f32x2 %0, %0, %1;"      : "+l"(acc) : "l"(v))

// ---------------------------------------------------------------------------
// conv0 (2->32, 3x3 pad1) + LIF0.  grid = 16 b * 32 o = 512 blocks, 256 thr.
// ---------------------------------------------------------------------------
__global__ void __launch_bounds__(256) k_conv0(const float* __restrict__ in,
                                               const float* __restrict__ W0, int t)
{
    int bid = blockIdx.x;
    int o = bid & 31, b = bid >> 5;
    float w[18];
#pragma unroll
    for (int i = 0; i < 18; i++) w[i] = W0[o * 18 + i];
    const float* x0 = in + (((long)(b * 16 + t)) << 13);

#pragma unroll 4
    for (int p = threadIdx.x; p < 4096; p += 256) {
        int y = p >> 6, x = p & 63;
        float acc = 0.f;
#pragma unroll
        for (int c = 0; c < 2; c++)
#pragma unroll
            for (int ky = 0; ky < 3; ky++) {
                int yy = y + ky - 1;
                if ((unsigned)yy < 64u)
#pragma unroll
                    for (int kx = 0; kx < 3; kx++) {
                        int xx = x + kx - 1;
                        if ((unsigned)xx < 64u) {
                            float v = x0[(c << 12) + (yy << 6) + xx];
                            v = fminf(fmaxf(v, 0.f), 1.f);
                            acc = fmaf(w[c * 9 + ky * 3 + kx], v, acc);
                        }
                    }
            }
        long idx = (((long)bid) << 12) + p;
        float vm = t ? g_vm0[idx] * DECAYF * (1.f - (float)g_s0[idx]) + acc : acc;
        g_vm0[idx] = vm;
        g_s0[idx]  = vm > 0.5f ? (unsigned char)1 : (unsigned char)0;
    }
}

// ---------------------------------------------------------------------------
// conv1 (32->64, 3x3) + LIF1 + fused 2x2 maxpool (binary OR) -> g_flatT.
// grid = 16 b * 8 tiles(16 rows x 32 cols) = 128 blocks, 256 threads.
// Thread: 8 och-pairs (16 och) x 8 pixels => 64 f32x2 accumulators.
// smem: all 64-och paired weights (72 KB) + spike halo bytes 32x18x36 (20.25KB)
// Weight LDS are warp-broadcast (whole warp shares og2); spikes: 10 byte-loads
// per (c,ky) reused across 3 kx  =>  FMA-issue bound.
// ---------------------------------------------------------------------------
__global__ void __launch_bounds__(256) k_conv1(const float* __restrict__ W1, int t)
{
    extern __shared__ unsigned char sh1[];
    unsigned long long* wsm = (unsigned long long*)sh1;   // [ck=288][p=32]
    unsigned char*      ssm = sh1 + 73728;                // [c=32][18][36]

    int bid  = blockIdx.x;
    int tile = bid & 7, b = bid >> 3;
    int y0 = (tile >> 1) << 4, x0 = (tile & 1) << 5;
    int tid = threadIdx.x;
    int og2 = tid >> 6;            // 0..3, constant per warp
    int pxg = tid & 63;
    int row = pxg & 15;
    int cg  = pxg >> 4;            // 0..3 (8-px column group)

    // weights: coalesced over ck
    for (int idx = tid; idx < 9216; idx += 256) {
        int p = idx / 288, ck = idx - p * 288;
        const float* wb = W1 + p * 576 + ck;
        wsm[ck * 32 + p] = pack2(wb[0], wb[288]);
    }
    // spike halo tile (zero padded)
    for (int idx = tid; idx < 20736; idx += 256) {
        int c = idx / 648, r = idx - c * 648;
        int yy = r / 36, xx = r - yy * 36;
        int y = y0 - 1 + yy, x = x0 - 1 + xx;
        unsigned char v = 0;
        if (xx < 34 && (unsigned)y < 64u && (unsigned)x < 64u)
            v = g_s0[(((b << 5) + c) << 12) + (y << 6) + x];
        ssm[idx] = v;
    }
    __syncthreads();

    unsigned long long acc[64];
#pragma unroll
    for (int i = 0; i < 64; i++) acc[i] = 0ull;

    for (int c = 0; c < 32; ++c) {
#pragma unroll
        for (int ky = 0; ky < 3; ++ky) {
            const unsigned char* rp = ssm + c * 648 + (row + ky) * 36 + cg * 8;
            unsigned long long sf2[10];
#pragma unroll
            for (int u = 0; u < 10; ++u) {
                float s = (float)rp[u];
                sf2[u] = pack2(s, s);
            }
#pragma unroll
            for (int kx = 0; kx < 3; ++kx) {
                const ulonglong2* wp =
                    (const ulonglong2*)(wsm + (c * 9 + ky * 3 + kx) * 32 + og2 * 8);
                ulonglong2 w01 = wp[0], w23 = wp[1], w45 = wp[2], w67 = wp[3];
                unsigned long long wv[8] = {w01.x, w01.y, w23.x, w23.y,
                                            w45.x, w45.y, w67.x, w67.y};
#pragma unroll
                for (int g = 0; g < 8; ++g)
#pragma unroll
                    for (int px = 0; px < 8; ++px)
                        FMA2(acc[g * 8 + px], wv[g], sf2[kx + px]);
            }
        }
    }

    // LIF1 + spike store + pooled bits (16 och x 4 x-pairs = 64 bits)
    int y = y0 + row, x = x0 + cg * 8;
    unsigned long long pool = 0ull;
#pragma unroll
    for (int g = 0; g < 8; ++g) {
        int o0 = og2 * 16 + 2 * g;
        long ibase = (((long)((b << 6) + o0)) << 12) + (y << 6) + x;
#pragma unroll
        for (int px = 0; px < 8; ++px) {
            float I0, I1; unpack2(acc[g * 8 + px], I0, I1);
            long i0 = ibase + px, i1 = i0 + 4096;
            float va = t ? g_vm1[i0] * DECAYF * (1.f - (float)g_s1[i0]) + I0 : I0;
            float vb = t ? g_vm1[i1] * DECAYF * (1.f - (float)g_s1[i1]) + I1 : I1;
            g_vm1[i0] = va; g_vm1[i1] = vb;
            unsigned sa = va > 0.5f ? 1u : 0u;
            unsigned sb = vb > 0.5f ? 1u : 0u;
            g_s1[i0] = (unsigned char)sa;
            g_s1[i1] = (unsigned char)sb;
            int xp = px >> 1;
            pool |= ((unsigned long long)sa) << ((2 * g) * 4 + xp);
            pool |= ((unsigned long long)sb) << ((2 * g + 1) * 4 + xp);
        }
    }
    pool |= __shfl_xor_sync(0xffffffffu, pool, 1);   // row partner (y ^ 1)
    if ((row & 1) == 0) {
        int py = y >> 1, pxb = x >> 1;
#pragma unroll
        for (int l = 0; l < 16; ++l) {
            int o = og2 * 16 + l;
#pragma unroll
            for (int xp = 0; xp < 4; ++xp) {
                int i = (o << 10) + (py << 5) + (pxb + xp);
                g_flatT[(i << 4) + b] = (float)((pool >> (l * 4 + xp)) & 1ull);
            }
        }
    }
}

// ---------------------------------------------------------------------------
// dense0 partials: out[b][j] = sum_i flat[b][i] * D0[j][i].
// grid = 8 j-tiles(64) x 64 i-splits(1024) = 512 blocks, 256 thr.
// Thread (jq,ig): 4 j rows x 8 batch-pairs = 32 f32x2 accs.
// Per i: 4 LDG (D0) + 8 LDS.64 (spike pairs) + 32 FFMA2 -> FMA/HBM balanced.
// ---------------------------------------------------------------------------
__global__ void __launch_bounds__(256) k_dense0(const float* __restrict__ D0)
{
    extern __shared__ float sh[];                        // 64 KB
    unsigned long long* sb2 = (unsigned long long*)sh;   // [p=8][i=1024]
    int jt = blockIdx.x & 7;
    int is = blockIdx.x >> 3;
    int tid = threadIdx.x;
    int jq = tid >> 4, ig = tid & 15;
    int j0 = (jt << 6) + (jq << 2);

    {   // stage flat chunk: [1024 i][16 b] -> pair-major [8 p][1024 i]
        const uint2* src = (const uint2*)(g_flatT + ((long)is << 14));
        uint2* dst = (uint2*)sb2;
        for (int n = tid; n < 8192; n += 256) {
            int i = n >> 3, p = n & 7;
            dst[p * 1024 + i] = src[n];
        }
    }
    __syncthreads();

    unsigned long long acc[32];
#pragma unroll
    for (int q = 0; q < 32; q++) acc[q] = 0ull;

    const float* dbase = D0 + ((long)j0 << 16) + (is << 10);
#pragma unroll 2
    for (int n = 0; n < 64; ++n) {
        int i = ig + (n << 4);
        float d0 = dbase[i];
        float d1 = dbase[65536 + i];
        float d2 = dbase[131072 + i];
        float d3 = dbase[196608 + i];
        unsigned long long dd0 = pack2(d0, d0), dd1 = pack2(d1, d1);
        unsigned long long dd2 = pack2(d2, d2), dd3 = pack2(d3, d3);
#pragma unroll
        for (int p = 0; p < 8; ++p) {
            unsigned long long s = sb2[(p << 10) + i];
            FMA2(acc[p],      dd0, s);
            FMA2(acc[8 + p],  dd1, s);
            FMA2(acc[16 + p], dd2, s);
            FMA2(acc[24 + p], dd3, s);
        }
    }
    // deterministic butterfly reduce across the 16 ig lanes
#pragma unroll
    for (int off = 8; off; off >>= 1)
#pragma unroll
        for (int q = 0; q < 32; q++) {
            unsigned long long v = __shfl_xor_sync(0xffffffffu, acc[q], off);
            ADD2(acc[q], v);
        }
    if (ig == 0) {
#pragma unroll
        for (int q = 0; q < 4; q++) {
            float* dst = g_part + (((is << 9) + j0 + q) << 4);
#pragma unroll
            for (int p = 0; p < 8; p++) {
                float a0, a1; unpack2(acc[q * 8 + p], a0, a1);
                dst[2 * p] = a0; dst[2 * p + 1] = a1;
            }
        }
    }
}

// ---------------------------------------------------------------------------
// lif2: reduce 64 partials per (j,b), LIF2 -> s2 floats. grid=32 x 256.
// ---------------------------------------------------------------------------
__global__ void __launch_bounds__(256) k_lif2(int t)
{
    int e = blockIdx.x * 256 + threadIdx.x;   // 8192 = 512 j * 16 b
    int j = e >> 4, b = e & 15;
    float I = 0.f;
#pragma unroll 8
    for (int is = 0; is < 64; is++) I += g_part[(is << 13) + (j << 4) + b];
    int idx = (b << 9) + j;
    float vm = t ? g_vm2[idx] * DECAYF * (1.f - g_s2f[idx]) + I : I;
    g_vm2[idx] = vm;
    g_s2f[idx] = vm > 0.5f ? 1.f : 0.f;
}

// ---------------------------------------------------------------------------
// dense1 + LIF3 + accumulate. 1 block, 512 thr; warp w = batch b.
// ---------------------------------------------------------------------------
__global__ void __launch_bounds__(512) k_dense1(const float* __restrict__ D1,
                                                float* __restrict__ out, int t)
{
    int tid = threadIdx.x;
    int b = tid >> 5, lane = tid & 31;
    float s[16];
#pragma unroll
    for (int u = 0; u < 16; u++) s[u] = g_s2f[(b << 9) + lane + (u << 5)];
    float mine = 0.f;
#pragma unroll
    for (int k = 0; k < 11; k++) {
        float acc = 0.f;
#pragma unroll
        for (int u = 0; u < 16; u++)
            acc = fmaf(s[u], D1[(k << 9) + lane + (u << 5)], acc);
#pragma unroll
        for (int off = 16; off; off >>= 1)
            acc += __shfl_xor_sync(0xffffffffu, acc, off);
        if (lane == k) mine = acc;
    }
    if (lane < 11) {
        int idx = b * 11 + lane;
        float vm = t ? g_vm3[idx] * DECAYF * (1.f - g_s3[idx]) + mine : mine;
        float sp = vm > 0.5f ? 1.f : 0.f;
        g_vm3[idx] = vm; g_s3[idx] = sp;
        float a = (t ? g_acc[idx] : 0.f) + sp;
        g_acc[idx] = a;
        if (t == 15) out[idx] = a * 0.0625f;
    }
}

// ---------------------------------------------------------------------------
extern "C" void kernel_launch(void* const* d_in, const int* in_sizes, int n_in,
                              void* d_out, int out_size)
{
    (void)in_sizes; (void)n_in; (void)out_size;
    const float* input = (const float*)d_in[0];
    const float* W0    = (const float*)d_in[1];
    const float* W1    = (const float*)d_in[2];
    const float* D0    = (const float*)d_in[3];
    const float* D1    = (const float*)d_in[4];
    float* out = (float*)d_out;

    cudaFuncSetAttribute(k_conv1,  cudaFuncAttributeMaxDynamicSharedMemorySize, 94464);
    cudaFuncSetAttribute(k_dense0, cudaFuncAttributeMaxDynamicSharedMemorySize, 65536);

    for (int t = 0; t < 16; t++) {
        k_conv0 <<<512, 256>>>(input, W0, t);
        k_conv1 <<<128, 256, 94464>>>(W1, t);
        k_dense0<<<512, 256, 65536>>>(D0);
        k_lif2  <<<32, 256>>>(t);
        k_dense1<<<1, 512>>>(D1, out, t);
    }
}